// round 9
// baseline (speedup 1.0000x reference)
#include <cuda_runtime.h>

// PlasticSynapse: out = clip(baseline*a + w*(1-a) + R*|kappa|*(post*pre + s*noise), 0, 1)
// Shapes: w,noise,out: [B=64, OUT=1024, IN=1024]; baseline,kappa: [OUT,IN];
//         R: [B]; pre: [B,IN]; post: [B,OUT].
// Pure HBM-bound elementwise: 768 MiB compulsory traffic.

#define B_   64
#define OUT_ 1024
#define IN_  1024
#define IN4_ (IN_ / 4)          // 256 float4 per row
#define ALPHA_W   0.01f
#define ONE_M_A   0.99f
#define SIGMA_W   0.14142135623730953f
#define WBOUND    1.0f

__global__ __launch_bounds__(256)
void plastic_synapse_kernel(const float4* __restrict__ w,
                            const float4* __restrict__ baseline,
                            const float*  __restrict__ R,
                            const float4* __restrict__ pre,
                            const float*  __restrict__ post,
                            const float4* __restrict__ kappa,
                            const float4* __restrict__ noise,
                            float4*       __restrict__ out)
{
    const int idx = blockIdx.x * blockDim.x + threadIdx.x;   // float4 index
    // idx = ((b * OUT_) + o) * IN4_ + i4 ; all powers of two
    const int i4 = idx & (IN4_ - 1);
    const int o  = (idx >> 8) & (OUT_ - 1);
    const int b  = idx >> 18;

    // Streamed (read-once) operands: evict-first so baseline/kappa stay in L2.
    const float4 w4 = __ldcs(&w[idx]);
    const float4 n4 = __ldcs(&noise[idx]);

    // Reused operands: default caching (L2-resident, 8 MiB total).
    const int oi = o * IN4_ + i4;
    const float4 bl = __ldg(&baseline[oi]);
    const float4 kp = __ldg(&kappa[oi]);
    const float4 pr = __ldg(&pre[b * IN4_ + i4]);
    const float  r  = __ldg(&R[b]);
    const float  p  = __ldg(&post[b * OUT_ + o]) ;
    const float  rp = r;          // R multiplies the whole plastic term

    float4 res;
    {
        float hebb = p * pr.x;
        float plas = rp * fabsf(kp.x) * fmaf(SIGMA_W, n4.x, hebb);
        float v = fmaf(bl.x, ALPHA_W, fmaf(w4.x, ONE_M_A, plas));
        res.x = fminf(fmaxf(v, 0.0f), WBOUND);
    }
    {
        float hebb = p * pr.y;
        float plas = rp * fabsf(kp.y) * fmaf(SIGMA_W, n4.y, hebb);
        float v = fmaf(bl.y, ALPHA_W, fmaf(w4.y, ONE_M_A, plas));
        res.y = fminf(fmaxf(v, 0.0f), WBOUND);
    }
    {
        float hebb = p * pr.z;
        float plas = rp * fabsf(kp.z) * fmaf(SIGMA_W, n4.z, hebb);
        float v = fmaf(bl.z, ALPHA_W, fmaf(w4.z, ONE_M_A, plas));
        res.z = fminf(fmaxf(v, 0.0f), WBOUND);
    }
    {
        float hebb = p * pr.w;
        float plas = rp * fabsf(kp.w) * fmaf(SIGMA_W, n4.w, hebb);
        float v = fmaf(bl.w, ALPHA_W, fmaf(w4.w, ONE_M_A, plas));
        res.w = fminf(fmaxf(v, 0.0f), WBOUND);
    }

    __stcs(&out[idx], res);
}

extern "C" void kernel_launch(void* const* d_in, const int* in_sizes, int n_in,
                              void* d_out, int out_size)
{
    // metadata order: w, baseline, R, pre, post, kappa, noise
    const float4* w        = (const float4*)d_in[0];
    const float4* baseline = (const float4*)d_in[1];
    const float*  R        = (const float*) d_in[2];
    const float4* pre      = (const float4*)d_in[3];
    const float*  post     = (const float*) d_in[4];
    const float4* kappa    = (const float4*)d_in[5];
    const float4* noise    = (const float4*)d_in[6];
    float4*       out      = (float4*)d_out;

    const int total4 = (B_ * OUT_ * IN_) / 4;   // 16,777,216
    const int threads = 256;
    const int blocks  = total4 / threads;       // 65,536

    plastic_synapse_kernel<<<blocks, threads>>>(w, baseline, R, pre, post,
                                                kappa, noise, out);
}